// round 17
// baseline (speedup 1.0000x reference)
#include <cuda_runtime.h>
#include <cstdint>

// Problem shape (fixed by the dataset): x is [128, 1, 512, 512] fp32 -> 128 rows x 262144.
#define ROWS     128
#define BINS1    2048      // top 11 bits of absbits (bit31 is 0 after abs-mask)
#define SLICES   16        // blocks per row for the streaming kernels
#define CAND_MAX 65536     // per-row candidate capacity (expected ~1700)
#define SCAP     8192      // smem candidate cache in refine kernel
#define TIE_CAP  512
#define PCAP     1024      // per-block smem candidate staging in k_part
#define SAMP_V4  16        // sample every 16th float4 (1/16 of elements)

// ---- static device scratch (no allocations allowed) ----
__device__ unsigned int g_hist[ROWS * BINS1];                       // 1 MB
__device__ unsigned int g_cand[(size_t)ROWS * CAND_MAX];            // 32 MB
__device__ unsigned int g_candcnt[ROWS];
__device__ unsigned int g_bin1[ROWS];
__device__ unsigned int g_need1[ROWS];
__device__ unsigned int g_blo[ROWS];    // conservative lower-bound bin (sampled)
__device__ unsigned int g_ok[ROWS];     // 1 = sparse histogram sufficed

// -------------------------------------------------------------------------
// Hillis-Steele block-wide suffix sum over NB shared entries (a,b ping-pong).
// Caller must __syncthreads() after filling a. Returns pointer holding result.
// -------------------------------------------------------------------------
template <int NB>
__device__ unsigned int* block_suffix(unsigned int* a, unsigned int* b) {
    unsigned int* src = a;
    unsigned int* dst = b;
    for (int off = 1; off < NB; off <<= 1) {
        for (int i = threadIdx.x; i < NB; i += blockDim.x) {
            unsigned int v = src[i];
            if (i + off < NB) v += src[i + off];
            dst[i] = v;
        }
        __syncthreads();
        unsigned int* t = src; src = dst; dst = t;
    }
    return src;
}

// -------------------------------------------------------------------------
// K0: zero accumulated scratch AND (blocks 0..ROWS-1) sample-estimate a
//     conservative per-row lower-bound bin b_lo (~4x margin over k).
// -------------------------------------------------------------------------
__global__ void k_init_sample(const float* __restrict__ x,
                              const int* __restrict__ kptr, int N) {
    // zeroing: 1024 blocks x 256 threads covers ROWS*BINS1 exactly
    int idx = blockIdx.x * blockDim.x + threadIdx.x;
    if (idx < ROWS * BINS1) g_hist[idx] = 0u;
    if (idx < ROWS) { g_candcnt[idx] = 0u; g_ok[idx] = 0u; }

    if (blockIdx.x >= ROWS) return;     // only first ROWS blocks sample

    __shared__ unsigned int a[BINS1];
    __shared__ unsigned int b[BINS1];
    __shared__ unsigned int s_blo;
    int row = blockIdx.x;
    for (int i = threadIdx.x; i < BINS1; i += blockDim.x) a[i] = 0u;
    if (threadIdx.x == 0) s_blo = 0u;
    __syncthreads();

    int nvec = N >> 2;
    int nsamp = nvec / SAMP_V4;                 // float4 samples per row
    const float4* xr = reinterpret_cast<const float4*>(x) + (size_t)row * nvec;
    for (int j = threadIdx.x; j < nsamp; j += blockDim.x) {
        float4 v = xr[(size_t)j * SAMP_V4];
        atomicAdd(&a[(__float_as_uint(v.x) & 0x7FFFFFFFu) >> 20], 1u);
        atomicAdd(&a[(__float_as_uint(v.y) & 0x7FFFFFFFu) >> 20], 1u);
        atomicAdd(&a[(__float_as_uint(v.z) & 0x7FFFFFFFu) >> 20], 1u);
        atomicAdd(&a[(__float_as_uint(v.w) & 0x7FFFFFFFu) >> 20], 1u);
    }
    __syncthreads();

    unsigned int* suf = block_suffix<BINS1>(a, b);
    unsigned int k = kptr ? (unsigned int)(*kptr) : 2048u;
    // sampled-count target: ~4x margin -> true count >= ~4k at chosen bin
    unsigned int need_s = (4u * k) / SAMP_V4 / 4u;   // = k/16 elements... careful:
    // sampling rate = 1/SAMP_V4 of elements; want true suffix ~ 4k
    // sampled target = 4k / SAMP_V4
    need_s = (4u * k) / SAMP_V4;
    if (need_s < 64u) need_s = 64u;

    for (int i = threadIdx.x; i < BINS1; i += blockDim.x) {
        unsigned int here = suf[i];
        unsigned int nxt  = (i + 1 < BINS1) ? suf[i + 1] : 0u;
        if (here >= need_s && nxt < need_s) s_blo = (unsigned int)i;
    }
    __syncthreads();
    if (threadIdx.x == 0) g_blo[row] = s_blo;   // 0 if nothing qualified
}

// -------------------------------------------------------------------------
// K1: per-row SPARSE histogram: only count bins >= b_lo (~3% of elements).
//     Pure streaming read otherwise. 16 blocks per row, 4-way batched loads.
// -------------------------------------------------------------------------
__global__ void __launch_bounds__(256) k_hist(const float* __restrict__ x, int N) {
    int row = blockIdx.x / SLICES;
    int sl  = blockIdx.x % SLICES;
    unsigned int blo = g_blo[row];

    __shared__ unsigned int sh[BINS1];
    for (int i = threadIdx.x; i < BINS1; i += blockDim.x) sh[i] = 0u;
    __syncthreads();

    int nvec = N >> 2;
    int svec = nvec / SLICES;
    const float4* xr = reinterpret_cast<const float4*>(x)
                     + (size_t)row * nvec + (size_t)sl * svec;

    const int T = blockDim.x;
    for (int i0 = threadIdx.x; i0 < svec; i0 += 4 * T) {
        float4 v[4];
#pragma unroll
        for (int u = 0; u < 4; u++) {
            int i = i0 + u * T;
            if (i < svec) v[u] = xr[i];
        }
#pragma unroll
        for (int u = 0; u < 4; u++) {
            int i = i0 + u * T;
            if (i >= svec) continue;
            unsigned int bx = (__float_as_uint(v[u].x) & 0x7FFFFFFFu) >> 20;
            unsigned int by = (__float_as_uint(v[u].y) & 0x7FFFFFFFu) >> 20;
            unsigned int bz = (__float_as_uint(v[u].z) & 0x7FFFFFFFu) >> 20;
            unsigned int bw = (__float_as_uint(v[u].w) & 0x7FFFFFFFu) >> 20;
            if (bx >= blo) atomicAdd(&sh[bx], 1u);
            if (by >= blo) atomicAdd(&sh[by], 1u);
            if (bz >= blo) atomicAdd(&sh[bz], 1u);
            if (bw >= blo) atomicAdd(&sh[bw], 1u);
        }
    }
    __syncthreads();

    unsigned int* gh = g_hist + (size_t)row * BINS1;
    for (int i = threadIdx.x; i < BINS1; i += blockDim.x)
        if (sh[i]) atomicAdd(&gh[i], sh[i]);
}

// -------------------------------------------------------------------------
// K2: per-row suffix scan -> threshold bin + need. Verifies the sparse
//     histogram covered >= k elements; if not, flags fallback and zeroes
//     the row histogram for the fix pass.
// -------------------------------------------------------------------------
__device__ __forceinline__ void pick_body(int row, unsigned int k, bool check_mode) {
    __shared__ unsigned int a[BINS1];
    __shared__ unsigned int b[BINS1];
    __shared__ int s_bin;
    __shared__ unsigned int s_need;

    if (threadIdx.x == 0) { s_bin = 0; s_need = 1u; }
    unsigned int* gh = g_hist + (size_t)row * BINS1;
    for (int i = threadIdx.x; i < BINS1; i += blockDim.x) a[i] = gh[i];
    __syncthreads();

    unsigned int* suf = block_suffix<BINS1>(a, b);

    if (check_mode) {
        unsigned int blo = g_blo[row];
        unsigned int total = suf[blo];          // everything counted
        if (total < k) {                        // sparse insufficient -> fallback
            for (int i = threadIdx.x; i < BINS1; i += blockDim.x) gh[i] = 0u;
            if (threadIdx.x == 0) g_ok[row] = 0u;
            return;
        }
        if (threadIdx.x == 0) g_ok[row] = 1u;
    }

    for (int i = threadIdx.x; i < BINS1; i += blockDim.x) {
        unsigned int here = suf[i];
        unsigned int nxt  = (i + 1 < BINS1) ? suf[i + 1] : 0u;
        if (here >= k && nxt < k) { s_bin = i; s_need = k - nxt; }
    }
    __syncthreads();
    if (threadIdx.x == 0) {
        g_bin1[row]  = (unsigned int)s_bin;
        g_need1[row] = s_need;
    }
}

__global__ void k_pick(const int* __restrict__ kptr) {
    unsigned int k = kptr ? (unsigned int)(*kptr) : 2048u;
    pick_body(blockIdx.x, k, true);
}

// K2b: fallback full histogram (early-exits per row in the common case)
__global__ void __launch_bounds__(256) k_hist_fix(const float* __restrict__ x, int N) {
    int row = blockIdx.x / SLICES;
    if (g_ok[row]) return;
    int sl  = blockIdx.x % SLICES;

    __shared__ unsigned int sh[BINS1];
    for (int i = threadIdx.x; i < BINS1; i += blockDim.x) sh[i] = 0u;
    __syncthreads();

    int nvec = N >> 2;
    int svec = nvec / SLICES;
    const float4* xr = reinterpret_cast<const float4*>(x)
                     + (size_t)row * nvec + (size_t)sl * svec;
    for (int i = threadIdx.x; i < svec; i += blockDim.x) {
        float4 v = xr[i];
        atomicAdd(&sh[(__float_as_uint(v.x) & 0x7FFFFFFFu) >> 20], 1u);
        atomicAdd(&sh[(__float_as_uint(v.y) & 0x7FFFFFFFu) >> 20], 1u);
        atomicAdd(&sh[(__float_as_uint(v.z) & 0x7FFFFFFFu) >> 20], 1u);
        atomicAdd(&sh[(__float_as_uint(v.w) & 0x7FFFFFFFu) >> 20], 1u);
    }
    __syncthreads();

    unsigned int* gh = g_hist + (size_t)row * BINS1;
    for (int i = threadIdx.x; i < BINS1; i += blockDim.x)
        if (sh[i]) atomicAdd(&gh[i], sh[i]);
}

// K2c: fallback pick (early-exits per row in the common case)
__global__ void k_pick_fix(const int* __restrict__ kptr) {
    if (g_ok[blockIdx.x]) return;
    unsigned int k = kptr ? (unsigned int)(*kptr) : 2048u;
    pick_body(blockIdx.x, k, false);
}

// -------------------------------------------------------------------------
// K3: write decided outputs (streaming stores), stage threshold-bin
//     candidate indices in SMEM, reserve a contiguous global range with ONE
//     atomicAdd per block, bulk-copy out. Candidate order is irrelevant
//     (k_refine breaks exact-bit ties by index VALUE, not arrival order).
// -------------------------------------------------------------------------
__global__ void __launch_bounds__(256) k_part(const float* __restrict__ x,
                                              float* __restrict__ out, int N) {
    int row = blockIdx.x / SLICES;
    int sl  = blockIdx.x % SLICES;
    unsigned int b1 = g_bin1[row];

    __shared__ unsigned int s_idx[PCAP];
    __shared__ unsigned int s_cnt;
    __shared__ unsigned int s_base;
    if (threadIdx.x == 0) s_cnt = 0u;
    __syncthreads();

    int nvec = N >> 2;
    int svec = nvec / SLICES;
    size_t base = (size_t)row * nvec + (size_t)sl * svec;
    const float4* xr  = reinterpret_cast<const float4*>(x) + base;
    float4*       owr = reinterpret_cast<float4*>(out) + base;
    unsigned int* cidx = g_cand + (size_t)row * CAND_MAX;

    const int T = blockDim.x;
    for (int i0 = threadIdx.x; i0 < svec; i0 += 4 * T) {
        float4 v[4];
#pragma unroll
        for (int u = 0; u < 4; u++) {
            int i = i0 + u * T;
            if (i < svec) v[u] = xr[i];      // 4 independent LDG.128 in flight
        }
#pragma unroll
        for (int u = 0; u < 4; u++) {
            int i = i0 + u * T;
            if (i >= svec) continue;
            int j0 = (sl * svec + i) << 2;   // element index within row
            float vi[4] = {v[u].x, v[u].y, v[u].z, v[u].w};
            float oo[4];
#pragma unroll
            for (int c = 0; c < 4; c++) {
                unsigned int bb  = __float_as_uint(vi[c]) & 0x7FFFFFFFu;
                unsigned int bin = bb >> 20;
                float o = 0.0f;
                if (bin > b1) {
                    o = vi[c];
                } else if (bin == b1) {
                    unsigned int p = atomicAdd(&s_cnt, 1u);   // smem, lat~30
                    if (p < PCAP) {
                        s_idx[p] = (unsigned int)(j0 + c);
                    } else {                                   // overflow (never expected)
                        unsigned int gp = atomicAdd(&g_candcnt[row], 1u);
                        if (gp < CAND_MAX) cidx[gp] = (unsigned int)(j0 + c);
                    }
                }
                oo[c] = o;
            }
            __stcs(owr + i, make_float4(oo[0], oo[1], oo[2], oo[3]));
        }
    }
    __syncthreads();

    unsigned int c = s_cnt; if (c > PCAP) c = PCAP;
    if (threadIdx.x == 0)
        s_base = atomicAdd(&g_candcnt[row], c);   // ONE global atomic per block
    __syncthreads();
    unsigned int gb = s_base;
    for (unsigned int i = threadIdx.x; i < c; i += blockDim.x)
        if (gb + i < CAND_MAX) cidx[gb + i] = s_idx[i];
}

// -------------------------------------------------------------------------
// K4: per-row refine over candidates (two 1024-bin radix passes -> exact
//     32-bit threshold T), then scatter kept candidates. Exact-bit ties at
//     T are broken by LOWEST index (matches jax.lax.top_k stability).
// -------------------------------------------------------------------------
__global__ void k_refine(const float* __restrict__ x, float* __restrict__ out, int N) {
    int row = blockIdx.x;
    __shared__ unsigned int sh_bits[SCAP];
    __shared__ unsigned int h1[1024];
    __shared__ unsigned int h2[1024];
    __shared__ unsigned int s_ties[TIE_CAP];
    __shared__ unsigned int s_tiecnt;
    __shared__ int s_b;
    __shared__ unsigned int s_need;

    unsigned int cnt = g_candcnt[row];
    if (cnt > CAND_MAX) cnt = CAND_MAX;
    unsigned int need = g_need1[row];
    unsigned int b1   = g_bin1[row];
    const unsigned int* cidx = g_cand + (size_t)row * CAND_MAX;
    const float* xr   = x   + (size_t)row * N;
    float*       orow = out + (size_t)row * N;
    bool in_s = (cnt <= SCAP);

    if (threadIdx.x == 0) { s_tiecnt = 0u; s_b = 0; s_need = 1u; }
    for (int i = threadIdx.x; i < 1024; i += blockDim.x) h1[i] = 0u;
    __syncthreads();

    // ---- level 2: bits[19:10] ----
    for (int i = threadIdx.x; i < (int)cnt; i += blockDim.x) {
        unsigned int bb = __float_as_uint(xr[cidx[i]]) & 0x7FFFFFFFu;
        if (in_s) sh_bits[i] = bb;
        atomicAdd(&h1[(bb >> 10) & 1023u], 1u);
    }
    __syncthreads();
    unsigned int* suf = block_suffix<1024>(h1, h2);
    for (int i = threadIdx.x; i < 1024; i += blockDim.x) {
        unsigned int here = suf[i];
        unsigned int nxt  = (i + 1 < 1024) ? suf[i + 1] : 0u;
        if (here >= need && nxt < need) { s_b = i; s_need = need - nxt; }
    }
    __syncthreads();
    unsigned int b2    = (unsigned int)s_b;
    unsigned int need2 = s_need;
    __syncthreads();

    // ---- level 3: bits[9:0] among b2 matches ----
    for (int i = threadIdx.x; i < 1024; i += blockDim.x) h1[i] = 0u;
    __syncthreads();
    for (int i = threadIdx.x; i < (int)cnt; i += blockDim.x) {
        unsigned int bb = in_s ? sh_bits[i]
                               : (__float_as_uint(xr[cidx[i]]) & 0x7FFFFFFFu);
        if (((bb >> 10) & 1023u) == b2) atomicAdd(&h1[bb & 1023u], 1u);
    }
    __syncthreads();
    suf = block_suffix<1024>(h1, h2);
    for (int i = threadIdx.x; i < 1024; i += blockDim.x) {
        unsigned int here = suf[i];
        unsigned int nxt  = (i + 1 < 1024) ? suf[i + 1] : 0u;
        if (here >= need2 && nxt < need2) { s_b = i; s_need = need2 - nxt; }
    }
    __syncthreads();
    unsigned int b3    = (unsigned int)s_b;
    unsigned int need3 = s_need;
    unsigned int tie_total = suf[b3] - ((b3 + 1 < 1024) ? suf[b3 + 1] : 0u);
    unsigned int T = (b1 << 20) | (b2 << 10) | b3;

    // ---- scatter kept candidates ----
    for (int i = threadIdx.x; i < (int)cnt; i += blockDim.x) {
        unsigned int id = cidx[i];
        float v = xr[id];
        unsigned int bb = __float_as_uint(v) & 0x7FFFFFFFu;
        if (bb > T) {
            orow[id] = v;
        } else if (bb == T) {
            if (need3 == tie_total) {
                orow[id] = v;            // all ties kept, order irrelevant
            } else {
                unsigned int t = atomicAdd(&s_tiecnt, 1u);
                if (t < TIE_CAP) s_ties[t] = id;
            }
        }
    }
    __syncthreads();

    // partial-ties case: keep the need3 LOWEST indices (stable like jax top_k)
    if (threadIdx.x == 0 && need3 != tie_total) {
        unsigned int tt = s_tiecnt; if (tt > TIE_CAP) tt = TIE_CAP;
        unsigned int nsel = (need3 < tt) ? need3 : tt;
        for (unsigned int s = 0; s < nsel; s++) {
            unsigned int best = s;
            for (unsigned int j = s + 1; j < tt; j++)
                if (s_ties[j] < s_ties[best]) best = j;
            unsigned int tmp = s_ties[s]; s_ties[s] = s_ties[best]; s_ties[best] = tmp;
            unsigned int id = s_ties[s];
            orow[id] = xr[id];
        }
    }
}

// -------------------------------------------------------------------------
extern "C" void kernel_launch(void* const* d_in, const int* in_sizes, int n_in,
                              void* d_out, int out_size) {
    const float* x = (const float*)d_in[0];
    const int* kptr = (n_in >= 2) ? (const int*)d_in[1] : nullptr;
    float* out = (float*)d_out;

    int total = in_sizes[0];
    int N = total / ROWS;   // 262144 for this dataset

    k_init_sample<<<(ROWS * BINS1 + 255) / 256, 256>>>(x, kptr, N);
    k_hist<<<ROWS * SLICES, 256>>>(x, N);
    k_pick<<<ROWS, 1024>>>(kptr);
    k_hist_fix<<<ROWS * SLICES, 256>>>(x, N);   // early-exits when sparse sufficed
    k_pick_fix<<<ROWS, 1024>>>(kptr);           // early-exits when sparse sufficed
    k_part<<<ROWS * SLICES, 256>>>(x, out, N);
    k_refine<<<ROWS, 1024>>>(x, out, N);
}